// round 1
// baseline (speedup 1.0000x reference)
#include <cuda_runtime.h>
#include <math.h>

#define HH 2048
#define WW 2048
#define NIMG 4
#define TOT (NIMG*HH*WW)

// ---------- device scratch (no allocations allowed) ----------
__device__ float        g_R[TOT];        // 64MB R buffer
__device__ float        g_gw[9];         // separable gaussian weights
__device__ unsigned int g_hist[2048];
__device__ unsigned int g_prefix;
__device__ unsigned int g_rank;
__device__ float        g_med;

// ---------- init: zero hist, derive 1D gaussian from provided 2D ----------
__global__ void k_init(const float* __restrict__ g2) {
    int t = threadIdx.x;
    for (int i = t; i < 2048; i += 256) g_hist[i] = 0;
    if (t == 0) {
        g_prefix = 0u;
        g_rank = (unsigned)((TOT - 1) / 2);   // 8388607
        // g2[i][j] = gn[i]*gn[j]  =>  gn[k] = g2[4][k]/sqrt(g2[4][4])
        double c = sqrt((double)g2[4*9 + 4]);
        for (int k = 0; k < 9; k++) g_gw[k] = (float)((double)g2[4*9 + k] / c);
    }
}

// ---------- fused Sobel + products + separable 9x9 gaussian + R ----------
__global__ __launch_bounds__(256) void k_harris(const float* __restrict__ x) {
    __shared__ float sx[42][44];         // x tile with +/-5 halo
    __shared__ float sp[3][40][42];      // Ixx,Iyy,Ixy with +/-4 halo
    __shared__ float sh[3][40][32];      // horizontally smoothed

    const int bx = blockIdx.x, by = blockIdx.y, n = blockIdx.z;
    const int r0 = by * 32, c0 = bx * 32;
    const float* __restrict__ xi = x + (size_t)n * HH * WW;
    const int t = threadIdx.x;

    // load x tile (zero-padded)
    for (int idx = t; idx < 42*42; idx += 256) {
        int i = idx / 42, j = idx % 42;
        int gr = r0 + i - 5, gc = c0 + j - 5;
        float v = 0.f;
        if (gr >= 0 && gr < HH && gc >= 0 && gc < WW) v = xi[(size_t)gr * WW + gc];
        sx[i][j] = v;
    }
    __syncthreads();

    // Sobel + products at positions rel (-4..35)x(-4..35); 0 outside image
    for (int idx = t; idx < 40*40; idx += 256) {
        int i = idx / 40, j = idx % 40;
        int gr = r0 + i - 4, gc = c0 + j - 4;
        float pxx = 0.f, pyy = 0.f, pxy = 0.f;
        if (gr >= 0 && gr < HH && gc >= 0 && gc < WW) {
            float a00 = sx[i][j],   a01 = sx[i][j+1],   a02 = sx[i][j+2];
            float a10 = sx[i+1][j],                     a12 = sx[i+1][j+2];
            float a20 = sx[i+2][j], a21 = sx[i+2][j+1], a22 = sx[i+2][j+2];
            float ix = (a02 - a00) + 2.f*(a12 - a10) + (a22 - a20);
            float iy = (a20 - a00) + 2.f*(a21 - a01) + (a22 - a02);
            pxx = ix*ix; pyy = iy*iy; pxy = ix*iy;
        }
        sp[0][i][j] = pxx; sp[1][i][j] = pyy; sp[2][i][j] = pxy;
    }
    __syncthreads();

    float w[9];
    #pragma unroll
    for (int k = 0; k < 9; k++) w[k] = g_gw[k];

    // horizontal gaussian: 40 rows x 32 cols, 3 channels
    for (int idx = t; idx < 40*32; idx += 256) {
        int i = idx / 32, j = idx % 32;
        float s0 = 0.f, s1 = 0.f, s2 = 0.f;
        #pragma unroll
        for (int k = 0; k < 9; k++) {
            float wk = w[k];
            s0 += wk * sp[0][i][j+k];
            s1 += wk * sp[1][i][j+k];
            s2 += wk * sp[2][i][j+k];
        }
        sh[0][i][j] = s0; sh[1][i][j] = s1; sh[2][i][j] = s2;
    }
    __syncthreads();

    // vertical gaussian + R
    for (int idx = t; idx < 32*32; idx += 256) {
        int r = idx / 32, c = idx % 32;
        float s0 = 0.f, s1 = 0.f, s2 = 0.f;
        #pragma unroll
        for (int k = 0; k < 9; k++) {
            float wk = w[k];
            s0 += wk * sh[0][r+k][c];
            s1 += wk * sh[1][r+k][c];
            s2 += wk * sh[2][r+k][c];
        }
        float det = s0 * s1 - s2 * s2;
        float tr  = s0 + s1;
        float R   = det - 0.05f * tr * tr;
        g_R[(size_t)n * HH * WW + (size_t)(r0 + r) * WW + (c0 + c)] = R;
    }
}

// ---------- radix-select histogram pass ----------
__global__ __launch_bounds__(256) void k_hist(int shift, int nbits) {
    __shared__ unsigned s_hist[2048];
    const int nb = 1 << nbits;
    for (int i = threadIdx.x; i < nb; i += 256) s_hist[i] = 0;
    __syncthreads();

    const unsigned pfx = g_prefix;
    const int hi = shift + nbits;
    const unsigned lane = threadIdx.x & 31;
    const float4* __restrict__ Rv = (const float4*)g_R;
    const size_t n4 = TOT / 4;
    const size_t stride = (size_t)gridDim.x * 256;

    for (size_t i4 = (size_t)blockIdx.x * 256 + threadIdx.x; i4 < n4; i4 += stride) {
        float4 v = Rv[i4];
        float vals[4] = {v.x, v.y, v.z, v.w};
        #pragma unroll
        for (int e = 0; e < 4; e++) {
            unsigned b = __float_as_uint(vals[e]);
            unsigned u = b ^ ((b & 0x80000000u) ? 0xFFFFFFFFu : 0x80000000u);
            bool match = (hi >= 32) || ((u >> hi) == (pfx >> hi));
            unsigned bin = (u >> shift) & (unsigned)(nb - 1);
            unsigned am = __ballot_sync(0xFFFFFFFFu, match);
            if (match) {
                unsigned peers = __match_any_sync(am, bin);
                if ((unsigned)(__ffs(peers) - 1) == lane)
                    atomicAdd(&s_hist[bin], (unsigned)__popc(peers));
            }
        }
    }
    __syncthreads();
    for (int i = threadIdx.x; i < nb; i += 256) {
        unsigned c = s_hist[i];
        if (c) atomicAdd(&g_hist[i], c);
    }
}

// ---------- scan + select bin, update prefix/rank, zero hist ----------
__global__ void k_select(int shift, int nbits) {
    __shared__ unsigned ssum[256];
    const int nb = 1 << nbits;
    const int per = nb >> 8;              // 8 or 4
    const int t = threadIdx.x;
    const unsigned pfx  = g_prefix;
    const unsigned rank = g_rank;

    unsigned local[8];
    unsigned sum = 0;
    for (int i = 0; i < per; i++) { local[i] = g_hist[t*per + i]; sum += local[i]; }
    ssum[t] = sum;
    __syncthreads();

    unsigned run = sum;
    for (int d = 1; d < 256; d <<= 1) {
        unsigned add = (t >= d) ? ssum[t - d] : 0u;
        __syncthreads();
        run += add;
        ssum[t] = run;
        __syncthreads();
    }
    unsigned before = run - sum;

    if (rank >= before && rank < run) {
        unsigned cum = before;
        for (int i = 0; i < per; i++) {
            if (rank < cum + local[i]) {
                unsigned bin = (unsigned)(t * per + i);
                unsigned np = pfx | (bin << shift);
                g_prefix = np;
                g_rank = rank - cum;
                if (shift == 0) {
                    unsigned bb = (np & 0x80000000u) ? (np ^ 0x80000000u) : ~np;
                    g_med = __uint_as_float(bb);
                }
                break;
            }
            cum += local[i];
        }
    }
    __syncthreads();
    for (int i = t; i < nb; i += 256) g_hist[i] = 0;
}

// ---------- threshold + 7x7 NMS (separable window max) ----------
__global__ __launch_bounds__(256) void k_pool(float* __restrict__ out) {
    __shared__ float sxt[38][40];
    __shared__ float srm[38][33];
    const int bx = blockIdx.x, by = blockIdx.y, n = blockIdx.z;
    const int r0 = by * 32, c0 = bx * 32;
    const float* __restrict__ Ri = g_R + (size_t)n * HH * WW;
    const float med = g_med;
    const float NEG_INF = __int_as_float(0xFF800000);

    for (int idx = threadIdx.x; idx < 38*38; idx += 256) {
        int i = idx / 38, j = idx % 38;
        int gr = r0 + i - 3, gc = c0 + j - 3;
        float v = NEG_INF;
        if (gr >= 0 && gr < HH && gc >= 0 && gc < WW) {
            float R = Ri[(size_t)gr * WW + gc];
            v = (R > med) ? R : 0.f;
        }
        sxt[i][j] = v;
    }
    __syncthreads();

    for (int idx = threadIdx.x; idx < 38*32; idx += 256) {
        int i = idx / 32, j = idx % 32;
        float m = sxt[i][j];
        #pragma unroll
        for (int k = 1; k < 7; k++) m = fmaxf(m, sxt[i][j+k]);
        srm[i][j] = m;
    }
    __syncthreads();

    for (int idx = threadIdx.x; idx < 32*32; idx += 256) {
        int r = idx / 32, c = idx % 32;
        float m = srm[r][c];
        #pragma unroll
        for (int k = 1; k < 7; k++) m = fmaxf(m, srm[r+k][c]);
        float xt = sxt[r+3][c+3];
        out[(size_t)n * HH * WW + (size_t)(r0 + r) * WW + (c0 + c)] = (xt == m) ? xt : 0.f;
    }
}

// ---------- launch ----------
extern "C" void kernel_launch(void* const* d_in, const int* in_sizes, int n_in,
                              void* d_out, int out_size) {
    const float* x     = (const float*)d_in[0];
    const float* gauss = (const float*)d_in[2];
    float* out = (float*)d_out;

    dim3 grid(WW/32, HH/32, NIMG);

    k_init<<<1, 256>>>(gauss);
    k_harris<<<grid, 256>>>(x);

    k_hist<<<2048, 256>>>(21, 11);
    k_select<<<1, 256>>>(21, 11);
    k_hist<<<2048, 256>>>(10, 11);
    k_select<<<1, 256>>>(10, 11);
    k_hist<<<2048, 256>>>(0, 10);
    k_select<<<1, 256>>>(0, 10);

    k_pool<<<grid, 256>>>(out);
}